// round 8
// baseline (speedup 1.0000x reference)
#include <cuda_runtime.h>

#define N_NODES 100000
#define DIM 64
#define N_EDGES 1250000
#define SCAN_BLK 1024
#define NUM_SCAN_BLKS ((N_NODES + SCAN_BLK - 1) / SCAN_BLK)   // 98

// ---------------- scratch (static device globals; no runtime allocation) ----
// zero-blob: [deg: N floats][cnt: N ints] — one memset clears both
__device__ unsigned char g_blob[(size_t)N_NODES * 8];
__device__ float g_dinv[N_NODES];
__device__ int   g_incl[N_NODES];
__device__ int   g_off[N_NODES + 1];
__device__ int   g_cursor[N_NODES];
__device__ int   g_bsum[128];
__device__ int2  g_edge[N_EDGES];          // (src, nrm-as-int) interleaved
__device__ float g_xw[(size_t)N_NODES * DIM];
__device__ float g_tmp[(size_t)N_NODES * DIM];

// ---------------- side stream for fork-join overlap (created at load time) --
struct SideStream {
    cudaStream_t s = nullptr;
    cudaEvent_t  evFork = nullptr, evJoin = nullptr;
    bool ok = false;
    SideStream() {
        ok = (cudaStreamCreateWithFlags(&s, cudaStreamNonBlocking) == cudaSuccess) &&
             (cudaEventCreateWithFlags(&evFork, cudaEventDisableTiming) == cudaSuccess) &&
             (cudaEventCreateWithFlags(&evJoin, cudaEventDisableTiming) == cudaSuccess);
    }
};
static SideStream g_ss;

// ---------------- structure-building kernels (run once per call) ------------

// degree accumulation + in-degree histogram, 4 edges per thread for MLP.
// ne divisible by 4 (1,250,000); row half at ei, col half at ei+ne (16B aligned).
__global__ void k_deg_cnt4(const int4* __restrict__ col4,
                           const float4* __restrict__ w4,
                           float* __restrict__ deg,
                           int* __restrict__ cnt, int ne4) {
    int e = blockIdx.x * blockDim.x + threadIdx.x;
    if (e >= ne4) return;
    int4   c = col4[e];
    float4 w = w4[e];
    atomicAdd(&deg[c.x], w.x);
    atomicAdd(&deg[c.y], w.y);
    atomicAdd(&deg[c.z], w.z);
    atomicAdd(&deg[c.w], w.w);
    atomicAdd(&cnt[c.x], 1);
    atomicAdd(&cnt[c.y], 1);
    atomicAdd(&cnt[c.z], 1);
    atomicAdd(&cnt[c.w], 1);
}

// per-1024-block inclusive scan of cnt (shfl-based; writes block totals)
__global__ void __launch_bounds__(SCAN_BLK) k_scan1(
        const int* __restrict__ cnt, int n) {
    __shared__ int wsum[32];
    int tid  = threadIdx.x;
    int lane = tid & 31;
    int wid  = tid >> 5;
    int gid  = blockIdx.x * SCAN_BLK + tid;

    int c = (gid < n) ? cnt[gid] : 0;
    int v = c;
#pragma unroll
    for (int d = 1; d < 32; d <<= 1) {
        int t = __shfl_up_sync(0xFFFFFFFFu, v, d);
        if (lane >= d) v += t;
    }
    if (lane == 31) wsum[wid] = v;
    __syncthreads();
    if (wid == 0) {
        int wv = wsum[lane];
#pragma unroll
        for (int d = 1; d < 32; d <<= 1) {
            int t = __shfl_up_sync(0xFFFFFFFFu, wv, d);
            if (lane >= d) wv += t;
        }
        wsum[lane] = wv;
    }
    __syncthreads();
    int incl = v + ((wid == 0) ? 0 : wsum[wid - 1]);
    if (gid < n) g_incl[gid] = incl;
    if (tid == SCAN_BLK - 1) g_bsum[blockIdx.x] = incl;   // block total
}

// fused scan2+scan3: each block locally scans the (<=128) block totals,
// then writes final offsets / cursor / dinv.
__global__ void k_scan3(const int* __restrict__ cnt,
                        const float* __restrict__ deg,
                        int n, int ne, int nb) {
    __shared__ int bs[128];
    int tid = threadIdx.x;
    if (tid < 128) bs[tid] = (tid < nb) ? g_bsum[tid] : 0;
    __syncthreads();
    // Hillis-Steele over 128 entries (block has 256 threads; only 128 active)
    for (int d = 1; d < 128; d <<= 1) {
        int t = (tid < 128 && tid >= d) ? bs[tid - d] : 0;
        __syncthreads();
        if (tid < 128) bs[tid] += t;
        __syncthreads();
    }
    int gid = blockIdx.x * blockDim.x + tid;
    if (gid < n) {
        int blk = gid >> 10;
        int ex_blk = (blk == 0) ? 0 : bs[blk - 1];
        int off = ex_blk + g_incl[gid] - cnt[gid];
        g_off[gid]    = off;
        g_cursor[gid] = off;
        g_dinv[gid]   = rsqrtf(1.0f + deg[gid]);   // self-loop folded in
    }
    if (gid == 0) g_off[n] = ne;
}

// scatter edges into CSR-by-destination buckets, 4 edges per thread for MLP
__global__ void k_scatter4(const int4* __restrict__ row4,
                           const int4* __restrict__ col4,
                           const float4* __restrict__ w4, int ne4) {
    int e = blockIdx.x * blockDim.x + threadIdx.x;
    if (e >= ne4) return;
    int4   r = row4[e];
    int4   c = col4[e];
    float4 w = w4[e];
    float dr0 = g_dinv[r.x], dr1 = g_dinv[r.y], dr2 = g_dinv[r.z], dr3 = g_dinv[r.w];
    float dc0 = g_dinv[c.x], dc1 = g_dinv[c.y], dc2 = g_dinv[c.z], dc3 = g_dinv[c.w];
    int p0 = atomicAdd(&g_cursor[c.x], 1);
    int p1 = atomicAdd(&g_cursor[c.y], 1);
    int p2 = atomicAdd(&g_cursor[c.z], 1);
    int p3 = atomicAdd(&g_cursor[c.w], 1);
    g_edge[p0] = make_int2(r.x, __float_as_int(dr0 * w.x * dc0));
    g_edge[p1] = make_int2(r.y, __float_as_int(dr1 * w.y * dc1));
    g_edge[p2] = make_int2(r.z, __float_as_int(dr2 * w.z * dc2));
    g_edge[p3] = make_int2(r.w, __float_as_int(dr3 * w.w * dc3));
}

// ---------------- per-layer kernels -----------------------------------------

// y[n,64] = x[n,64] @ W[64,64]; 128 threads, 128-row tile, 8x8 reg tile.
__global__ void __launch_bounds__(128) k_gemm64(
        const float* __restrict__ x,
        const float* __restrict__ W,
        float* __restrict__ y, int n) {
    __shared__ float Ws[64 * 64];     // 16 KB, [k][c]
    __shared__ float xs[64 * 128];    // 32 KB, transposed [k][row_local]
    int tid = threadIdx.x;
    int base = blockIdx.x * 128;

    {
        const float4* Wv = (const float4*)W;
        float4* Wd = (float4*)Ws;
#pragma unroll
        for (int i = 0; i < 8; i++) Wd[tid + 128 * i] = Wv[tid + 128 * i];
    }
    {
        int row = base + tid;
        int rc = (row < n) ? row : (n - 1);
        const float4* xv = (const float4*)(x + (size_t)rc * DIM);
#pragma unroll
        for (int j = 0; j < 16; j++) {
            float4 v = xv[j];
            xs[(j * 4 + 0) * 128 + tid] = v.x;
            xs[(j * 4 + 1) * 128 + tid] = v.y;
            xs[(j * 4 + 2) * 128 + tid] = v.z;
            xs[(j * 4 + 3) * 128 + tid] = v.w;
        }
    }
    __syncthreads();

    int r0 = (tid >> 3) << 3;
    int c0 = (tid & 7) << 3;

    float acc[8][8];
#pragma unroll
    for (int i = 0; i < 8; i++)
#pragma unroll
        for (int j = 0; j < 8; j++) acc[i][j] = 0.0f;

#pragma unroll 2
    for (int k = 0; k < 64; k++) {
        float4 a0 = *(const float4*)&xs[k * 128 + r0];
        float4 a1 = *(const float4*)&xs[k * 128 + r0 + 4];
        float4 b0 = *(const float4*)&Ws[k * 64 + c0];
        float4 b1 = *(const float4*)&Ws[k * 64 + c0 + 4];
        float av[8] = {a0.x, a0.y, a0.z, a0.w, a1.x, a1.y, a1.z, a1.w};
        float bv[8] = {b0.x, b0.y, b0.z, b0.w, b1.x, b1.y, b1.z, b1.w};
#pragma unroll
        for (int i = 0; i < 8; i++)
#pragma unroll
            for (int j = 0; j < 8; j++)
                acc[i][j] = fmaf(av[i], bv[j], acc[i][j]);
    }

#pragma unroll
    for (int i = 0; i < 8; i++) {
        int row = base + r0 + i;
        if (row < n) {
            float4* yp = (float4*)(y + (size_t)row * DIM + c0);
            yp[0] = make_float4(acc[i][0], acc[i][1], acc[i][2], acc[i][3]);
            yp[1] = make_float4(acc[i][4], acc[i][5], acc[i][6], acc[i][7]);
        }
    }
}

// pull aggregation: one warp per node; half-warp per edge, float4 gathers,
// int2 edge records. Fuses self-loop, bias, temp = 0.9*out + 0.1*prev.
__global__ void k_agg(const float4* __restrict__ xw4,
                      const float4* __restrict__ prev4,
                      float4* __restrict__ dst4,
                      const float4* __restrict__ b4, int n) {
    int warp = (blockIdx.x * blockDim.x + threadIdx.x) >> 5;
    int lane = threadIdx.x & 31;
    if (warp >= n) return;
    int lane16 = lane & 15;
    int half   = lane >> 4;

    float4 acc = make_float4(0.f, 0.f, 0.f, 0.f);
    int s = g_off[warp];
    int e = g_off[warp + 1];

    int i = s + half;
    for (; i + 2 < e; i += 4) {
        int2 e0 = g_edge[i];
        int2 e1 = g_edge[i + 2];
        float4 v0 = xw4[(size_t)e0.x * 16 + lane16];
        float4 v1 = xw4[(size_t)e1.x * 16 + lane16];
        float w0 = __int_as_float(e0.y);
        float w1 = __int_as_float(e1.y);
        acc.x = fmaf(v0.x, w0, acc.x); acc.y = fmaf(v0.y, w0, acc.y);
        acc.z = fmaf(v0.z, w0, acc.z); acc.w = fmaf(v0.w, w0, acc.w);
        acc.x = fmaf(v1.x, w1, acc.x); acc.y = fmaf(v1.y, w1, acc.y);
        acc.z = fmaf(v1.z, w1, acc.z); acc.w = fmaf(v1.w, w1, acc.w);
    }
    if (i < e) {
        int2 e0 = g_edge[i];
        float4 v0 = xw4[(size_t)e0.x * 16 + lane16];
        float w0 = __int_as_float(e0.y);
        acc.x = fmaf(v0.x, w0, acc.x); acc.y = fmaf(v0.y, w0, acc.y);
        acc.z = fmaf(v0.z, w0, acc.z); acc.w = fmaf(v0.w, w0, acc.w);
    }

    acc.x += __shfl_xor_sync(0xFFFFFFFFu, acc.x, 16);
    acc.y += __shfl_xor_sync(0xFFFFFFFFu, acc.y, 16);
    acc.z += __shfl_xor_sync(0xFFFFFFFFu, acc.z, 16);
    acc.w += __shfl_xor_sync(0xFFFFFFFFu, acc.w, 16);

    if (half == 0) {
        float di = g_dinv[warp];
        float selfw = di * di;
        float4 sv = xw4[(size_t)warp * 16 + lane16];
        acc.x = fmaf(sv.x, selfw, acc.x);
        acc.y = fmaf(sv.y, selfw, acc.y);
        acc.z = fmaf(sv.z, selfw, acc.z);
        acc.w = fmaf(sv.w, selfw, acc.w);
        float4 bv = b4[lane16];
        float4 pv = prev4[(size_t)warp * 16 + lane16];
        float4 o;
        o.x = 0.9f * (acc.x + bv.x) + 0.1f * pv.x;
        o.y = 0.9f * (acc.y + bv.y) + 0.1f * pv.y;
        o.z = 0.9f * (acc.z + bv.z) + 0.1f * pv.z;
        o.w = 0.9f * (acc.w + bv.w) + 0.1f * pv.w;
        dst4[(size_t)warp * 16 + lane16] = o;
    }
}

// ---------------- launch ------------------------------------------------------

extern "C" void kernel_launch(void* const* d_in, const int* in_sizes, int n_in,
                              void* d_out, int out_size) {
    const float* x    = (const float*)d_in[0];   // [N, 64] fp32
    const int*   ei   = (const int*)d_in[1];     // [2, E] int32
    const float* ew   = (const float*)d_in[2];   // [E] fp32
    const float* W1   = (const float*)d_in[3];
    const float* b1   = (const float*)d_in[4];
    const float* W2   = (const float*)d_in[5];
    const float* b2   = (const float*)d_in[6];
    float*       out  = (float*)d_out;

    const int n  = in_sizes[0] / DIM;   // 100000
    const int ne = in_sizes[1] / 2;     // 1250000
    const int ne4 = ne / 4;

    unsigned char* blob = nullptr;
    float *xw = nullptr, *tmp = nullptr;
    cudaGetSymbolAddress((void**)&blob, g_blob);
    cudaGetSymbolAddress((void**)&xw,   g_xw);
    cudaGetSymbolAddress((void**)&tmp,  g_tmp);

    float* degp = (float*)blob;
    int*   cntp = (int*)(blob + (size_t)n * 4);

    const int T = 256;
    const int gemm_grid = (n + 127) / 128;
    const int agg_grid  = (n * 32 + T - 1) / T;

    // ---- fork: layer-1 GEMM (depends only on x, W1) runs beside the build
    bool forked = g_ss.ok;
    if (forked) {
        cudaEventRecord(g_ss.evFork, 0);
        cudaStreamWaitEvent(g_ss.s, g_ss.evFork, 0);
        k_gemm64<<<gemm_grid, 128, 0, g_ss.s>>>(x, W1, xw, n);
        cudaEventRecord(g_ss.evJoin, g_ss.s);
    }

    // ---- build CSR-by-destination (shared across both layers) ----
    cudaMemsetAsync(blob, 0, (size_t)n * 8, 0);
    k_deg_cnt4<<<(ne4 + T - 1) / T, T>>>((const int4*)(ei + ne),
                                         (const float4*)ew, degp, cntp, ne4);
    k_scan1   <<<NUM_SCAN_BLKS, SCAN_BLK>>>(cntp, n);
    k_scan3   <<<(n + T - 1) / T, T>>>(cntp, degp, n, ne, NUM_SCAN_BLKS);
    k_scatter4<<<(ne4 + T - 1) / T, T>>>((const int4*)ei, (const int4*)(ei + ne),
                                         (const float4*)ew, ne4);

    if (forked) {
        cudaStreamWaitEvent(0, g_ss.evJoin, 0);
    } else {
        k_gemm64<<<gemm_grid, 128>>>(x, W1, xw, n);
    }

    // ---- layer 1 aggregation ----
    k_agg<<<agg_grid, T>>>((const float4*)xw, (const float4*)x,
                           (float4*)tmp, (const float4*)b1, n);

    // ---- layer 2 ----
    k_gemm64<<<gemm_grid, 128>>>(tmp, W2, xw, n);
    k_agg<<<agg_grid, T>>>((const float4*)xw, (const float4*)tmp,
                           (float4*)out, (const float4*)b2, n);
}

// round 10
// speedup vs baseline: 1.1324x; 1.1324x over previous
#include <cuda_runtime.h>

#define N_NODES 100000
#define DIM 64
#define N_EDGES 1250000
#define SCAN_BLK 1024
#define NUM_SCAN_BLKS ((N_NODES + SCAN_BLK - 1) / SCAN_BLK)   // 98

// Q26 fixed-point degree packing: bits [0,44) = sum(w)*2^26, bits [44,64) = count
#define DEG_SHIFT 44
#define DEG_MASK  ((1ULL << DEG_SHIFT) - 1ULL)
#define Q26       67108864.0f          // 2^26
#define INV_Q26   (1.0f / 67108864.0f)

// ---------------- scratch (static device globals; no runtime allocation) ----
__device__ unsigned long long g_packed[N_NODES];   // zeroed each call
__device__ float g_dinv[N_NODES];
__device__ int   g_incl[N_NODES];
__device__ int   g_off[N_NODES + 1];
__device__ int   g_cursor[N_NODES];
__device__ int   g_bsum[128];
__device__ int   g_src[N_EDGES];
__device__ float g_nrm[N_EDGES];
__device__ float g_xw[(size_t)N_NODES * DIM];
__device__ float g_tmp[(size_t)N_NODES * DIM];

// ---------------- side stream for fork-join overlap (created at load time) --
struct SideStream {
    cudaStream_t s = nullptr;
    cudaEvent_t  evFork = nullptr, evJoin = nullptr;
    bool ok = false;
    SideStream() {
        ok = (cudaStreamCreateWithFlags(&s, cudaStreamNonBlocking) == cudaSuccess) &&
             (cudaEventCreateWithFlags(&evFork, cudaEventDisableTiming) == cudaSuccess) &&
             (cudaEventCreateWithFlags(&evJoin, cudaEventDisableTiming) == cudaSuccess);
    }
};
static SideStream g_ss;

// ---------------- structure-building kernels (run once per call) ------------

// ONE 64-bit atomic per edge: packed (cnt << 44) | (w in Q26)
__global__ void k_deg_cnt(const int* __restrict__ ei,
                          const float* __restrict__ w, int ne) {
    int e = blockIdx.x * blockDim.x + threadIdx.x;
    if (e >= ne) return;
    int c = ei[ne + e];                // col (target)
    unsigned long long v = (1ULL << DEG_SHIFT) |
        (unsigned long long)__float2uint_rn(w[e] * Q26);
    atomicAdd(&g_packed[c], v);
}

// per-1024-block inclusive scan of cnt (shfl-based; writes block totals)
__global__ void __launch_bounds__(SCAN_BLK) k_scan1(int n) {
    __shared__ int wsum[32];
    int tid  = threadIdx.x;
    int lane = tid & 31;
    int wid  = tid >> 5;
    int gid  = blockIdx.x * SCAN_BLK + tid;

    int c = (gid < n) ? (int)(g_packed[gid] >> DEG_SHIFT) : 0;
    int v = c;
#pragma unroll
    for (int d = 1; d < 32; d <<= 1) {
        int t = __shfl_up_sync(0xFFFFFFFFu, v, d);
        if (lane >= d) v += t;
    }
    if (lane == 31) wsum[wid] = v;
    __syncthreads();
    if (wid == 0) {
        int wv = wsum[lane];
#pragma unroll
        for (int d = 1; d < 32; d <<= 1) {
            int t = __shfl_up_sync(0xFFFFFFFFu, wv, d);
            if (lane >= d) wv += t;
        }
        wsum[lane] = wv;
    }
    __syncthreads();
    int incl = v + ((wid == 0) ? 0 : wsum[wid - 1]);
    if (gid < n) g_incl[gid] = incl;
    if (tid == SCAN_BLK - 1) g_bsum[blockIdx.x] = incl;   // block total
}

// fused scan2+scan3: each block locally scans the (<=128) block totals,
// then writes final offsets / cursor / dinv.
__global__ void k_scan3(int n, int ne, int nb) {
    __shared__ int bs[128];
    int tid = threadIdx.x;
    if (tid < 128) bs[tid] = (tid < nb) ? g_bsum[tid] : 0;
    __syncthreads();
    for (int d = 1; d < 128; d <<= 1) {
        int t = (tid < 128 && tid >= d) ? bs[tid - d] : 0;
        __syncthreads();
        if (tid < 128) bs[tid] += t;
        __syncthreads();
    }
    int gid = blockIdx.x * blockDim.x + tid;
    if (gid < n) {
        unsigned long long p = g_packed[gid];
        int   cnt = (int)(p >> DEG_SHIFT);
        float deg = (float)(p & DEG_MASK) * INV_Q26;
        int blk = gid >> 10;
        int ex_blk = (blk == 0) ? 0 : bs[blk - 1];
        int off = ex_blk + g_incl[gid] - cnt;
        g_off[gid]    = off;
        g_cursor[gid] = off;
        g_dinv[gid]   = rsqrtf(1.0f + deg);   // self-loop folded in
    }
    if (gid == 0) g_off[n] = ne;
}

// scatter edges into CSR-by-destination buckets, with precomputed norm
__global__ void k_scatter(const int* __restrict__ ei,
                          const float* __restrict__ w, int ne) {
    int e = blockIdx.x * blockDim.x + threadIdx.x;
    if (e >= ne) return;
    int r = ei[e];
    int c = ei[ne + e];
    float nn = g_dinv[r] * w[e] * g_dinv[c];
    int pos = atomicAdd(&g_cursor[c], 1);
    g_src[pos] = r;
    g_nrm[pos] = nn;
}

// ---------------- per-layer kernels -----------------------------------------

// y[n,64] = x[n,64] @ W[64,64]; 128 threads, 128-row tile, 8x8 reg tile.
__global__ void __launch_bounds__(128) k_gemm64(
        const float* __restrict__ x,
        const float* __restrict__ W,
        float* __restrict__ y, int n) {
    __shared__ float Ws[64 * 64];     // 16 KB, [k][c]
    __shared__ float xs[64 * 128];    // 32 KB, transposed [k][row_local]
    int tid = threadIdx.x;
    int base = blockIdx.x * 128;

    {
        const float4* Wv = (const float4*)W;
        float4* Wd = (float4*)Ws;
#pragma unroll
        for (int i = 0; i < 8; i++) Wd[tid + 128 * i] = Wv[tid + 128 * i];
    }
    {
        int row = base + tid;
        int rc = (row < n) ? row : (n - 1);
        const float4* xv = (const float4*)(x + (size_t)rc * DIM);
#pragma unroll
        for (int j = 0; j < 16; j++) {
            float4 v = xv[j];
            xs[(j * 4 + 0) * 128 + tid] = v.x;
            xs[(j * 4 + 1) * 128 + tid] = v.y;
            xs[(j * 4 + 2) * 128 + tid] = v.z;
            xs[(j * 4 + 3) * 128 + tid] = v.w;
        }
    }
    __syncthreads();

    int r0 = (tid >> 3) << 3;
    int c0 = (tid & 7) << 3;

    float acc[8][8];
#pragma unroll
    for (int i = 0; i < 8; i++)
#pragma unroll
        for (int j = 0; j < 8; j++) acc[i][j] = 0.0f;

#pragma unroll 2
    for (int k = 0; k < 64; k++) {
        float4 a0 = *(const float4*)&xs[k * 128 + r0];
        float4 a1 = *(const float4*)&xs[k * 128 + r0 + 4];
        float4 b0 = *(const float4*)&Ws[k * 64 + c0];
        float4 b1 = *(const float4*)&Ws[k * 64 + c0 + 4];
        float av[8] = {a0.x, a0.y, a0.z, a0.w, a1.x, a1.y, a1.z, a1.w};
        float bv[8] = {b0.x, b0.y, b0.z, b0.w, b1.x, b1.y, b1.z, b1.w};
#pragma unroll
        for (int i = 0; i < 8; i++)
#pragma unroll
            for (int j = 0; j < 8; j++)
                acc[i][j] = fmaf(av[i], bv[j], acc[i][j]);
    }

#pragma unroll
    for (int i = 0; i < 8; i++) {
        int row = base + r0 + i;
        if (row < n) {
            float4* yp = (float4*)(y + (size_t)row * DIM + c0);
            yp[0] = make_float4(acc[i][0], acc[i][1], acc[i][2], acc[i][3]);
            yp[1] = make_float4(acc[i][4], acc[i][5], acc[i][6], acc[i][7]);
        }
    }
}

// pull aggregation (exact R5 version): one warp per node; half-warp per edge,
// float4 gathers, separate src/nrm arrays. Fuses self-loop, bias,
// temp = 0.9*out + 0.1*prev.
__global__ void k_agg(const float4* __restrict__ xw4,
                      const float4* __restrict__ prev4,
                      float4* __restrict__ dst4,
                      const float4* __restrict__ b4, int n) {
    int warp = (blockIdx.x * blockDim.x + threadIdx.x) >> 5;
    int lane = threadIdx.x & 31;
    if (warp >= n) return;
    int lane16 = lane & 15;
    int half   = lane >> 4;

    float4 acc = make_float4(0.f, 0.f, 0.f, 0.f);
    int s = g_off[warp];
    int e = g_off[warp + 1];

    int i = s + half;
    // 2x unrolled (each step covers this half's edges i and i+2)
    for (; i + 2 < e; i += 4) {
        int   s0 = g_src[i];
        int   s1 = g_src[i + 2];
        float w0 = g_nrm[i];
        float w1 = g_nrm[i + 2];
        float4 v0 = xw4[(size_t)s0 * 16 + lane16];
        float4 v1 = xw4[(size_t)s1 * 16 + lane16];
        acc.x = fmaf(v0.x, w0, acc.x); acc.y = fmaf(v0.y, w0, acc.y);
        acc.z = fmaf(v0.z, w0, acc.z); acc.w = fmaf(v0.w, w0, acc.w);
        acc.x = fmaf(v1.x, w1, acc.x); acc.y = fmaf(v1.y, w1, acc.y);
        acc.z = fmaf(v1.z, w1, acc.z); acc.w = fmaf(v1.w, w1, acc.w);
    }
    if (i < e) {
        int   s0 = g_src[i];
        float w0 = g_nrm[i];
        float4 v0 = xw4[(size_t)s0 * 16 + lane16];
        acc.x = fmaf(v0.x, w0, acc.x); acc.y = fmaf(v0.y, w0, acc.y);
        acc.z = fmaf(v0.z, w0, acc.z); acc.w = fmaf(v0.w, w0, acc.w);
    }

    // combine the two halves
    acc.x += __shfl_xor_sync(0xFFFFFFFFu, acc.x, 16);
    acc.y += __shfl_xor_sync(0xFFFFFFFFu, acc.y, 16);
    acc.z += __shfl_xor_sync(0xFFFFFFFFu, acc.z, 16);
    acc.w += __shfl_xor_sync(0xFFFFFFFFu, acc.w, 16);

    if (half == 0) {
        float di = g_dinv[warp];
        float selfw = di * di;
        float4 sv = xw4[(size_t)warp * 16 + lane16];
        acc.x = fmaf(sv.x, selfw, acc.x);
        acc.y = fmaf(sv.y, selfw, acc.y);
        acc.z = fmaf(sv.z, selfw, acc.z);
        acc.w = fmaf(sv.w, selfw, acc.w);
        float4 bv = b4[lane16];
        float4 pv = prev4[(size_t)warp * 16 + lane16];
        float4 o;
        o.x = 0.9f * (acc.x + bv.x) + 0.1f * pv.x;
        o.y = 0.9f * (acc.y + bv.y) + 0.1f * pv.y;
        o.z = 0.9f * (acc.z + bv.z) + 0.1f * pv.z;
        o.w = 0.9f * (acc.w + bv.w) + 0.1f * pv.w;
        dst4[(size_t)warp * 16 + lane16] = o;
    }
}

// ---------------- launch ------------------------------------------------------

extern "C" void kernel_launch(void* const* d_in, const int* in_sizes, int n_in,
                              void* d_out, int out_size) {
    const float* x    = (const float*)d_in[0];   // [N, 64] fp32
    const int*   ei   = (const int*)d_in[1];     // [2, E] int32
    const float* ew   = (const float*)d_in[2];   // [E] fp32
    const float* W1   = (const float*)d_in[3];
    const float* b1   = (const float*)d_in[4];
    const float* W2   = (const float*)d_in[5];
    const float* b2   = (const float*)d_in[6];
    float*       out  = (float*)d_out;

    const int n  = in_sizes[0] / DIM;   // 100000
    const int ne = in_sizes[1] / 2;     // 1250000

    void* packedp = nullptr;
    float *xw = nullptr, *tmp = nullptr;
    cudaGetSymbolAddress(&packedp, g_packed);
    cudaGetSymbolAddress((void**)&xw,  g_xw);
    cudaGetSymbolAddress((void**)&tmp, g_tmp);

    const int T = 256;
    const int gemm_grid = (n + 127) / 128;
    const int agg_grid  = (n * 32 + T - 1) / T;

    // ---- fork: layer-1 GEMM (depends only on x, W1) runs beside the build
    bool forked = g_ss.ok;
    if (forked) {
        cudaEventRecord(g_ss.evFork, 0);
        cudaStreamWaitEvent(g_ss.s, g_ss.evFork, 0);
        k_gemm64<<<gemm_grid, 128, 0, g_ss.s>>>(x, W1, xw, n);
        cudaEventRecord(g_ss.evJoin, g_ss.s);
    }

    // ---- build CSR-by-destination (shared across both layers) ----
    cudaMemsetAsync(packedp, 0, (size_t)n * 8, 0);
    k_deg_cnt<<<(ne + T - 1) / T, T>>>(ei, ew, ne);
    k_scan1  <<<NUM_SCAN_BLKS, SCAN_BLK>>>(n);
    k_scan3  <<<(n + T - 1) / T, T>>>(n, ne, NUM_SCAN_BLKS);
    k_scatter<<<(ne + T - 1) / T, T>>>(ei, ew, ne);

    if (forked) {
        cudaStreamWaitEvent(0, g_ss.evJoin, 0);
    } else {
        k_gemm64<<<gemm_grid, 128>>>(x, W1, xw, n);
    }

    // ---- layer 1 aggregation ----
    k_agg<<<agg_grid, T>>>((const float4*)xw, (const float4*)x,
                           (float4*)tmp, (const float4*)b1, n);

    // ---- layer 2 ----
    k_gemm64<<<gemm_grid, 128>>>(tmp, W2, xw, n);
    k_agg<<<agg_grid, T>>>((const float4*)xw, (const float4*)tmp,
                           (float4*)out, (const float4*)b2, n);
}

// round 13
// speedup vs baseline: 1.2135x; 1.0717x over previous
#include <cuda_runtime.h>
#include <cuda_fp16.h>

#define N_NODES 100000
#define DIM 64
#define N_EDGES 1250000
#define SCAN_BLK 1024
#define NUM_SCAN_BLKS ((N_NODES + SCAN_BLK - 1) / SCAN_BLK)   // 98

// Q26 fixed-point degree packing: bits [0,44) = sum(w)*2^26, bits [44,64) = count
#define DEG_SHIFT 44
#define DEG_MASK  ((1ULL << DEG_SHIFT) - 1ULL)
#define Q26       67108864.0f          // 2^26
#define INV_Q26   (1.0f / 67108864.0f)

// ---------------- scratch (static device globals; no runtime allocation) ----
__device__ unsigned long long g_packed[N_NODES];   // zeroed each call
__device__ float g_dinv[N_NODES];
__device__ int   g_incl[N_NODES];
__device__ int   g_off[N_NODES + 1];
__device__ int   g_cursor[N_NODES];
__device__ int   g_bsum[128];
__device__ int   g_src[N_EDGES];
__device__ float g_nrm[N_EDGES];
__device__ __half2 g_xwh[(size_t)N_NODES * 32];    // xw in fp16 (32 half2/row)
__device__ float g_tmp[(size_t)N_NODES * DIM];

// ---------------- side stream for fork-join overlap (created at load time) --
struct SideStream {
    cudaStream_t s = nullptr;
    cudaEvent_t  evFork = nullptr, evJoin = nullptr;
    bool ok = false;
    SideStream() {
        ok = (cudaStreamCreateWithFlags(&s, cudaStreamNonBlocking) == cudaSuccess) &&
             (cudaEventCreateWithFlags(&evFork, cudaEventDisableTiming) == cudaSuccess) &&
             (cudaEventCreateWithFlags(&evJoin, cudaEventDisableTiming) == cudaSuccess);
    }
};
static SideStream g_ss;

// ---------------- structure-building kernels (run once per call) ------------

// ONE 64-bit atomic per edge: packed (cnt << 44) | (w in Q26)
__global__ void k_deg_cnt(const int* __restrict__ ei,
                          const float* __restrict__ w, int ne) {
    int e = blockIdx.x * blockDim.x + threadIdx.x;
    if (e >= ne) return;
    int c = ei[ne + e];                // col (target)
    unsigned long long v = (1ULL << DEG_SHIFT) |
        (unsigned long long)__float2uint_rn(w[e] * Q26);
    atomicAdd(&g_packed[c], v);
}

// per-1024-block inclusive scan of cnt (shfl-based; writes block totals)
__global__ void __launch_bounds__(SCAN_BLK) k_scan1(int n) {
    __shared__ int wsum[32];
    int tid  = threadIdx.x;
    int lane = tid & 31;
    int wid  = tid >> 5;
    int gid  = blockIdx.x * SCAN_BLK + tid;

    int c = (gid < n) ? (int)(g_packed[gid] >> DEG_SHIFT) : 0;
    int v = c;
#pragma unroll
    for (int d = 1; d < 32; d <<= 1) {
        int t = __shfl_up_sync(0xFFFFFFFFu, v, d);
        if (lane >= d) v += t;
    }
    if (lane == 31) wsum[wid] = v;
    __syncthreads();
    if (wid == 0) {
        int wv = wsum[lane];
#pragma unroll
        for (int d = 1; d < 32; d <<= 1) {
            int t = __shfl_up_sync(0xFFFFFFFFu, wv, d);
            if (lane >= d) wv += t;
        }
        wsum[lane] = wv;
    }
    __syncthreads();
    int incl = v + ((wid == 0) ? 0 : wsum[wid - 1]);
    if (gid < n) g_incl[gid] = incl;
    if (tid == SCAN_BLK - 1) g_bsum[blockIdx.x] = incl;   // block total
}

// fused scan2+scan3: each block locally scans the (<=128) block totals,
// then writes final offsets / cursor / dinv.
__global__ void k_scan3(int n, int ne, int nb) {
    __shared__ int bs[128];
    int tid = threadIdx.x;
    if (tid < 128) bs[tid] = (tid < nb) ? g_bsum[tid] : 0;
    __syncthreads();
    for (int d = 1; d < 128; d <<= 1) {
        int t = (tid < 128 && tid >= d) ? bs[tid - d] : 0;
        __syncthreads();
        if (tid < 128) bs[tid] += t;
        __syncthreads();
    }
    int gid = blockIdx.x * blockDim.x + tid;
    if (gid < n) {
        unsigned long long p = g_packed[gid];
        int   cnt = (int)(p >> DEG_SHIFT);
        float deg = (float)(p & DEG_MASK) * INV_Q26;
        int blk = gid >> 10;
        int ex_blk = (blk == 0) ? 0 : bs[blk - 1];
        int off = ex_blk + g_incl[gid] - cnt;
        g_off[gid]    = off;
        g_cursor[gid] = off;
        g_dinv[gid]   = rsqrtf(1.0f + deg);   // self-loop folded in
    }
    if (gid == 0) g_off[n] = ne;
}

// scatter edges into CSR-by-destination buckets, with precomputed norm
__global__ void k_scatter(const int* __restrict__ ei,
                          const float* __restrict__ w, int ne) {
    int e = blockIdx.x * blockDim.x + threadIdx.x;
    if (e >= ne) return;
    int r = ei[e];
    int c = ei[ne + e];
    float nn = g_dinv[r] * w[e] * g_dinv[c];
    int pos = atomicAdd(&g_cursor[c], 1);
    g_src[pos] = r;
    g_nrm[pos] = nn;
}

// ---------------- per-layer kernels -----------------------------------------

// y[n,64] = x[n,64] @ W[64,64], OUTPUT IN FP16 (half2).
// 128 threads, 128-row tile, 8x8 reg tile, fp32 accumulate.
__global__ void __launch_bounds__(128) k_gemm64h(
        const float* __restrict__ x,
        const float* __restrict__ W,
        __half2* __restrict__ y, int n) {
    __shared__ float Ws[64 * 64];     // 16 KB, [k][c]
    __shared__ float xs[64 * 128];    // 32 KB, transposed [k][row_local]
    int tid = threadIdx.x;
    int base = blockIdx.x * 128;

    {
        const float4* Wv = (const float4*)W;
        float4* Wd = (float4*)Ws;
#pragma unroll
        for (int i = 0; i < 8; i++) Wd[tid + 128 * i] = Wv[tid + 128 * i];
    }
    {
        int row = base + tid;
        int rc = (row < n) ? row : (n - 1);
        const float4* xv = (const float4*)(x + (size_t)rc * DIM);
#pragma unroll
        for (int j = 0; j < 16; j++) {
            float4 v = xv[j];
            xs[(j * 4 + 0) * 128 + tid] = v.x;
            xs[(j * 4 + 1) * 128 + tid] = v.y;
            xs[(j * 4 + 2) * 128 + tid] = v.z;
            xs[(j * 4 + 3) * 128 + tid] = v.w;
        }
    }
    __syncthreads();

    int r0 = (tid >> 3) << 3;
    int c0 = (tid & 7) << 3;

    float acc[8][8];
#pragma unroll
    for (int i = 0; i < 8; i++)
#pragma unroll
        for (int j = 0; j < 8; j++) acc[i][j] = 0.0f;

#pragma unroll 2
    for (int k = 0; k < 64; k++) {
        float4 a0 = *(const float4*)&xs[k * 128 + r0];
        float4 a1 = *(const float4*)&xs[k * 128 + r0 + 4];
        float4 b0 = *(const float4*)&Ws[k * 64 + c0];
        float4 b1 = *(const float4*)&Ws[k * 64 + c0 + 4];
        float av[8] = {a0.x, a0.y, a0.z, a0.w, a1.x, a1.y, a1.z, a1.w};
        float bv[8] = {b0.x, b0.y, b0.z, b0.w, b1.x, b1.y, b1.z, b1.w};
#pragma unroll
        for (int i = 0; i < 8; i++)
#pragma unroll
            for (int j = 0; j < 8; j++)
                acc[i][j] = fmaf(av[i], bv[j], acc[i][j]);
    }

#pragma unroll
    for (int i = 0; i < 8; i++) {
        int row = base + r0 + i;
        if (row < n) {
            __half2 h[4];
            h[0] = __floats2half2_rn(acc[i][0], acc[i][1]);
            h[1] = __floats2half2_rn(acc[i][2], acc[i][3]);
            h[2] = __floats2half2_rn(acc[i][4], acc[i][5]);
            h[3] = __floats2half2_rn(acc[i][6], acc[i][7]);
            // row stride = 32 half2; c0/2 is a multiple of 4 -> 16B aligned
            *(uint4*)&y[(size_t)row * 32 + (c0 >> 1)] = *(uint4*)h;
        }
    }
}

// pull aggregation: one warp per node; half-warp per edge, fp16 row gathers
// (uint2 = 4 dims per lane), fp32 accumulate. Fuses self-loop, bias,
// temp = 0.9*out + 0.1*prev.
__global__ void k_agg(const uint2* __restrict__ xwh,
                      const float4* __restrict__ prev4,
                      float4* __restrict__ dst4,
                      const float4* __restrict__ b4, int n) {
    int warp = (blockIdx.x * blockDim.x + threadIdx.x) >> 5;
    int lane = threadIdx.x & 31;
    if (warp >= n) return;
    int lane16 = lane & 15;
    int half   = lane >> 4;

    float4 acc = make_float4(0.f, 0.f, 0.f, 0.f);
    int s = g_off[warp];
    int e = g_off[warp + 1];

    int i = s + half;
    // 2x unrolled (each step covers this half's edges i and i+2)
    for (; i + 2 < e; i += 4) {
        int   s0 = g_src[i];
        int   s1 = g_src[i + 2];
        float w0 = g_nrm[i];
        float w1 = g_nrm[i + 2];
        uint2 g0 = xwh[(size_t)s0 * 16 + lane16];   // 16 uint2 per row
        uint2 g1 = xwh[(size_t)s1 * 16 + lane16];
        float2 p00 = __half22float2(*(__half2*)&g0.x);
        float2 p01 = __half22float2(*(__half2*)&g0.y);
        float2 p10 = __half22float2(*(__half2*)&g1.x);
        float2 p11 = __half22float2(*(__half2*)&g1.y);
        acc.x = fmaf(p00.x, w0, acc.x); acc.y = fmaf(p00.y, w0, acc.y);
        acc.z = fmaf(p01.x, w0, acc.z); acc.w = fmaf(p01.y, w0, acc.w);
        acc.x = fmaf(p10.x, w1, acc.x); acc.y = fmaf(p10.y, w1, acc.y);
        acc.z = fmaf(p11.x, w1, acc.z); acc.w = fmaf(p11.y, w1, acc.w);
    }
    if (i < e) {
        int   s0 = g_src[i];
        float w0 = g_nrm[i];
        uint2 g0 = xwh[(size_t)s0 * 16 + lane16];
        float2 p00 = __half22float2(*(__half2*)&g0.x);
        float2 p01 = __half22float2(*(__half2*)&g0.y);
        acc.x = fmaf(p00.x, w0, acc.x); acc.y = fmaf(p00.y, w0, acc.y);
        acc.z = fmaf(p01.x, w0, acc.z); acc.w = fmaf(p01.y, w0, acc.w);
    }

    // combine the two halves
    acc.x += __shfl_xor_sync(0xFFFFFFFFu, acc.x, 16);
    acc.y += __shfl_xor_sync(0xFFFFFFFFu, acc.y, 16);
    acc.z += __shfl_xor_sync(0xFFFFFFFFu, acc.z, 16);
    acc.w += __shfl_xor_sync(0xFFFFFFFFu, acc.w, 16);

    if (half == 0) {
        float di = g_dinv[warp];
        float selfw = di * di;
        uint2 gs = xwh[(size_t)warp * 16 + lane16];
        float2 s0 = __half22float2(*(__half2*)&gs.x);
        float2 s1 = __half22float2(*(__half2*)&gs.y);
        acc.x = fmaf(s0.x, selfw, acc.x);
        acc.y = fmaf(s0.y, selfw, acc.y);
        acc.z = fmaf(s1.x, selfw, acc.z);
        acc.w = fmaf(s1.y, selfw, acc.w);
        float4 bv = b4[lane16];
        float4 pv = prev4[(size_t)warp * 16 + lane16];
        float4 o;
        o.x = 0.9f * (acc.x + bv.x) + 0.1f * pv.x;
        o.y = 0.9f * (acc.y + bv.y) + 0.1f * pv.y;
        o.z = 0.9f * (acc.z + bv.z) + 0.1f * pv.z;
        o.w = 0.9f * (acc.w + bv.w) + 0.1f * pv.w;
        dst4[(size_t)warp * 16 + lane16] = o;
    }
}

// ---------------- launch ------------------------------------------------------

extern "C" void kernel_launch(void* const* d_in, const int* in_sizes, int n_in,
                              void* d_out, int out_size) {
    const float* x    = (const float*)d_in[0];   // [N, 64] fp32
    const int*   ei   = (const int*)d_in[1];     // [2, E] int32
    const float* ew   = (const float*)d_in[2];   // [E] fp32
    const float* W1   = (const float*)d_in[3];
    const float* b1   = (const float*)d_in[4];
    const float* W2   = (const float*)d_in[5];
    const float* b2   = (const float*)d_in[6];
    float*       out  = (float*)d_out;

    const int n  = in_sizes[0] / DIM;   // 100000
    const int ne = in_sizes[1] / 2;     // 1250000

    void* packedp = nullptr;
    __half2* xwh = nullptr;
    float* tmp = nullptr;
    cudaGetSymbolAddress(&packedp, g_packed);
    cudaGetSymbolAddress((void**)&xwh, g_xwh);
    cudaGetSymbolAddress((void**)&tmp, g_tmp);

    const int T = 256;
    const int gemm_grid = (n + 127) / 128;
    const int agg_grid  = (n * 32 + T - 1) / T;

    // ---- fork: layer-1 GEMM (depends only on x, W1) runs beside the build
    bool forked = g_ss.ok;
    if (forked) {
        cudaEventRecord(g_ss.evFork, 0);
        cudaStreamWaitEvent(g_ss.s, g_ss.evFork, 0);
        k_gemm64h<<<gemm_grid, 128, 0, g_ss.s>>>(x, W1, xwh, n);
        cudaEventRecord(g_ss.evJoin, g_ss.s);
    }

    // ---- build CSR-by-destination (shared across both layers) ----
    cudaMemsetAsync(packedp, 0, (size_t)n * 8, 0);
    k_deg_cnt<<<(ne + T - 1) / T, T>>>(ei, ew, ne);
    k_scan1  <<<NUM_SCAN_BLKS, SCAN_BLK>>>(n);
    k_scan3  <<<(n + T - 1) / T, T>>>(n, ne, NUM_SCAN_BLKS);
    k_scatter<<<(ne + T - 1) / T, T>>>(ei, ew, ne);

    if (forked) {
        cudaStreamWaitEvent(0, g_ss.evJoin, 0);
    } else {
        k_gemm64h<<<gemm_grid, 128>>>(x, W1, xwh, n);
    }

    // ---- layer 1 aggregation ----
    k_agg<<<agg_grid, T>>>((const uint2*)xwh, (const float4*)x,
                           (float4*)tmp, (const float4*)b1, n);

    // ---- layer 2 ----
    k_gemm64h<<<gemm_grid, 128>>>(tmp, W2, xwh, n);
    k_agg<<<agg_grid, T>>>((const uint2*)xwh, (const float4*)tmp,
                           (float4*)out, (const float4*)b2, n);
}